// round 3
// baseline (speedup 1.0000x reference)
#include <cuda_runtime.h>
#include <math.h>
#include <float.h>
#include <stdint.h>

// Problem constants
#define B   4
#define T   1024
#define F   1024
#define H   16
#define D   64
#define MROWS (B*T)       // 4096

// Tensor-core GEMM tiling
#define BM 128
#define BN 64
#define BK 16

// Scratch (allocation-free rule: __device__ globals)
__device__ float g_q[(size_t)B*T*F];
__device__ float g_k[(size_t)B*T*F];
__device__ float g_v[(size_t)B*T*F];
__device__ float g_x[(size_t)B*T*F];
__device__ int   g_mask_code;

// ---------------------------------------------------------------------------
// Mask dtype detection (bool masks may arrive as u8 / i32 / f32)
// ---------------------------------------------------------------------------
__global__ void detect_mask(const unsigned int* __restrict__ m)
{
    unsigned int w = m[blockIdx.x * blockDim.x + threadIdx.x];
    int f = 0;
    if (w == 0x3F800000u)      f = 2;
    else if (w > 1u)           f = 1;
    if (f) atomicOr(&g_mask_code, f);
}

// ---------------------------------------------------------------------------
// tf32 helpers
// ---------------------------------------------------------------------------
__device__ __forceinline__ float tf32_rna(float x) {
    uint32_t r;
    asm("cvt.rna.tf32.f32 %0, %1;" : "=r"(r) : "f"(x));
    return __uint_as_float(r);
}

__device__ __forceinline__ void mma8(float* c, const uint32_t* a, const uint32_t* b) {
    asm volatile(
        "mma.sync.aligned.m16n8k8.row.col.f32.tf32.tf32.f32 "
        "{%0,%1,%2,%3},{%4,%5,%6,%7},{%8,%9},{%0,%1,%2,%3};"
        : "+f"(c[0]), "+f"(c[1]), "+f"(c[2]), "+f"(c[3])
        : "r"(a[0]), "r"(a[1]), "r"(a[2]), "r"(a[3]), "r"(b[0]), "r"(b[1]));
}

// ---------------------------------------------------------------------------
// Generic tensor-core GEMM.
//   C[m,n] (+epilogue) = sum_k A[m,k] * B(k,n)
//   A: row-major, optionally concatenated (A0 for k<Asplit, A1 after), lda.
//   B: NT=false -> B[k*ldb + n] ; NT=true -> B[n*ldb + k]
//   Per-z offsets: ptr += (z&3)*sL + (z>>2)*sH  (works for all launches here).
//   X3: 3-term tf32 split for fp32-grade accuracy.
//   EPI: 0 = +bias[n]; 1 = *alpha; 2 = plain; 3 = +bias[n] + resid[m*ldc+n]
// Block: 128x64 tile, 256 threads (8 warps, 32x32 warp tiles), BK=16.
// ---------------------------------------------------------------------------
template<bool NT, bool X3, int EPI>
__global__ void __launch_bounds__(256) mma_gemm(
    const float* __restrict__ A0, const float* __restrict__ A1, int Asplit, int lda,
    long saL, long saH,
    const float* __restrict__ Bm, int ldb, long sbL, long sbH,
    float* __restrict__ C, int ldc, long scL, long scH,
    int K, const float* __restrict__ bias, const float* __restrict__ resid,
    float alpha)
{
    const int z = blockIdx.z;
    const long zoffA = (long)(z & 3) * saL + (long)(z >> 2) * saH;
    A0 += zoffA;  A1 += zoffA;
    Bm += (long)(z & 3) * sbL + (long)(z >> 2) * sbH;
    C  += (long)(z & 3) * scL + (long)(z >> 2) * scH;

    const int tile_m = blockIdx.y * BM;
    const int tile_n = blockIdx.x * BN;

    const int t    = threadIdx.x;
    const int warp = t >> 5;
    const int lane = t & 31;
    const int g    = lane >> 2;   // group id (0..7)
    const int t4   = lane & 3;    // thread in group
    const int wm   = warp >> 1;   // 0..3  -> 32-row slab
    const int wn   = warp & 1;    // 0..1  -> 32-col slab

    constexpr int PL = X3 ? 2 : 1;
    __shared__ float As[PL][BK][BM + 4];
    __shared__ float Bs[PL][BK][BN + 4];

    float acc[2][4][4] = {};

    for (int kt = 0; kt < K; kt += BK) {
        // ---- stage A tile: As[k][m] ----
        const float* Ab;  int kc;
        if (kt < Asplit) { Ab = A0; kc = kt; } else { Ab = A1; kc = kt - Asplit; }
        #pragma unroll
        for (int rep = 0; rep < 2; rep++) {
            int m  = (t >> 2) + rep * 64;
            int k4 = (t & 3) * 4;
            float4 a = *(const float4*)(Ab + (size_t)(tile_m + m) * lda + kc + k4);
            float v[4] = {a.x, a.y, a.z, a.w};
            #pragma unroll
            for (int j = 0; j < 4; j++) {
                float hi = tf32_rna(v[j]);
                As[0][k4 + j][m] = hi;
                if (X3) As[1][k4 + j][m] = v[j] - hi;
            }
        }
        // ---- stage B tile: Bs[k][n] ----
        if (NT) {
            int n  = t >> 2;
            int k4 = (t & 3) * 4;
            float4 b = *(const float4*)(Bm + (size_t)(tile_n + n) * ldb + kt + k4);
            float v[4] = {b.x, b.y, b.z, b.w};
            #pragma unroll
            for (int j = 0; j < 4; j++) {
                float hi = tf32_rna(v[j]);
                Bs[0][k4 + j][n] = hi;
                if (X3) Bs[1][k4 + j][n] = v[j] - hi;
            }
        } else {
            int k  = t >> 4;
            int n4 = (t & 15) * 4;
            float4 b = *(const float4*)(Bm + (size_t)(kt + k) * ldb + tile_n + n4);
            float v[4] = {b.x, b.y, b.z, b.w};
            #pragma unroll
            for (int j = 0; j < 4; j++) {
                float hi = tf32_rna(v[j]);
                Bs[0][k][n4 + j] = hi;
                if (X3) Bs[1][k][n4 + j] = v[j] - hi;
            }
        }
        __syncthreads();

        // ---- compute: two k8 steps ----
        #pragma unroll
        for (int kk = 0; kk < BK; kk += 8) {
            uint32_t ah[2][4], bh[4][2];
            #pragma unroll
            for (int i = 0; i < 2; i++) {
                int rb = wm * 32 + i * 16;
                ah[i][0] = __float_as_uint(As[0][kk + t4    ][rb + g    ]);
                ah[i][1] = __float_as_uint(As[0][kk + t4    ][rb + g + 8]);
                ah[i][2] = __float_as_uint(As[0][kk + t4 + 4][rb + g    ]);
                ah[i][3] = __float_as_uint(As[0][kk + t4 + 4][rb + g + 8]);
            }
            #pragma unroll
            for (int j = 0; j < 4; j++) {
                int cb = wn * 32 + j * 8;
                bh[j][0] = __float_as_uint(Bs[0][kk + t4    ][cb + g]);
                bh[j][1] = __float_as_uint(Bs[0][kk + t4 + 4][cb + g]);
            }
            if (X3) {
                uint32_t al[2][4], bl[4][2];
                #pragma unroll
                for (int i = 0; i < 2; i++) {
                    int rb = wm * 32 + i * 16;
                    al[i][0] = __float_as_uint(As[1][kk + t4    ][rb + g    ]);
                    al[i][1] = __float_as_uint(As[1][kk + t4    ][rb + g + 8]);
                    al[i][2] = __float_as_uint(As[1][kk + t4 + 4][rb + g    ]);
                    al[i][3] = __float_as_uint(As[1][kk + t4 + 4][rb + g + 8]);
                }
                #pragma unroll
                for (int j = 0; j < 4; j++) {
                    int cb = wn * 32 + j * 8;
                    bl[j][0] = __float_as_uint(Bs[1][kk + t4    ][cb + g]);
                    bl[j][1] = __float_as_uint(Bs[1][kk + t4 + 4][cb + g]);
                }
                #pragma unroll
                for (int i = 0; i < 2; i++)
                    #pragma unroll
                    for (int j = 0; j < 4; j++) {
                        mma8(acc[i][j], al[i], bh[j]);
                        mma8(acc[i][j], ah[i], bl[j]);
                    }
            }
            #pragma unroll
            for (int i = 0; i < 2; i++)
                #pragma unroll
                for (int j = 0; j < 4; j++)
                    mma8(acc[i][j], ah[i], bh[j]);
        }
        __syncthreads();
    }

    // ---- epilogue ----
    #pragma unroll
    for (int i = 0; i < 2; i++) {
        #pragma unroll
        for (int j = 0; j < 4; j++) {
            int row = tile_m + wm * 32 + i * 16 + g;
            int col = tile_n + wn * 32 + j * 8 + t4 * 2;
            #pragma unroll
            for (int half = 0; half < 2; half++) {
                int r = row + half * 8;
                float c0 = acc[i][j][half * 2 + 0];
                float c1 = acc[i][j][half * 2 + 1];
                if (EPI == 0) { c0 += bias[col]; c1 += bias[col + 1]; }
                if (EPI == 1) { c0 *= alpha;     c1 *= alpha; }
                if (EPI == 3) {
                    c0 += bias[col]     + resid[(size_t)r * ldc + col];
                    c1 += bias[col + 1] + resid[(size_t)r * ldc + col + 1];
                }
                float2 o = make_float2(c0, c1);
                *(float2*)(C + (size_t)r * ldc + col) = o;
            }
        }
    }
}

// ---------------------------------------------------------------------------
// Masked softmax (in place on attn) + mask-zeroing + query_mask scale.
// ---------------------------------------------------------------------------
__device__ __forceinline__ float warpMax(float v) {
    #pragma unroll
    for (int o = 16; o; o >>= 1) v = fmaxf(v, __shfl_xor_sync(0xffffffffu, v, o));
    return v;
}
__device__ __forceinline__ float warpSum(float v) {
    #pragma unroll
    for (int o = 16; o; o >>= 1) v += __shfl_xor_sync(0xffffffffu, v, o);
    return v;
}

__global__ void softmax_mask(float* __restrict__ attn,
                             const void* __restrict__ mask,
                             const float* __restrict__ query_mask)
{
    const int r  = blockIdx.x;
    const int z  = r >> 10;
    const int bb = z & 3;
    const int i  = r & 1023;
    const size_t base = (size_t)r * T;
    const int t = threadIdx.x;

    float4 s = ((const float4*)(attn + base))[t];

    int m0, m1, m2, m3;
    const int code = g_mask_code;
    if (code & 2) {
        float4 mf = ((const float4*)((const float*)mask + base))[t];
        m0 = (mf.x != 0.f); m1 = (mf.y != 0.f); m2 = (mf.z != 0.f); m3 = (mf.w != 0.f);
    } else if (code & 1) {
        uchar4 mc = ((const uchar4*)((const unsigned char*)mask + base))[t];
        m0 = mc.x; m1 = mc.y; m2 = mc.z; m3 = mc.w;
    } else {
        int4 mi = ((const int4*)((const int*)mask + base))[t];
        m0 = mi.x; m1 = mi.y; m2 = mi.z; m3 = mi.w;
    }

    float v0 = m0 ? -FLT_MAX : s.x;
    float v1 = m1 ? -FLT_MAX : s.y;
    float v2 = m2 ? -FLT_MAX : s.z;
    float v3 = m3 ? -FLT_MAX : s.w;
    float lm = fmaxf(fmaxf(v0, v1), fmaxf(v2, v3));

    __shared__ float red[8];
    float wm = warpMax(lm);
    if ((t & 31) == 0) red[t >> 5] = wm;
    __syncthreads();
    float bmax = red[0];
    #pragma unroll
    for (int w = 1; w < 8; w++) bmax = fmaxf(bmax, red[w]);
    __syncthreads();

    float p0 = m0 ? 0.f : __expf(s.x - bmax);
    float p1 = m1 ? 0.f : __expf(s.y - bmax);
    float p2 = m2 ? 0.f : __expf(s.z - bmax);
    float p3 = m3 ? 0.f : __expf(s.w - bmax);

    float ws = warpSum(p0 + p1 + p2 + p3);
    if ((t & 31) == 0) red[t >> 5] = ws;
    __syncthreads();
    float bsum = 0.f;
    #pragma unroll
    for (int w = 0; w < 8; w++) bsum += red[w];

    float qm  = query_mask[bb * T + i];
    float inv = (bsum > 0.f) ? (qm / bsum) : 0.f;

    float4 o;
    o.x = p0 * inv; o.y = p1 * inv; o.z = p2 * inv; o.w = p3 * inv;
    ((float4*)(attn + base))[t] = o;
}

// ---------------------------------------------------------------------------
extern "C" void kernel_launch(void* const* d_in, const int* in_sizes, int n_in,
                              void* d_out, int out_size)
{
    const float* query       = (const float*)d_in[0];
    const float* key         = (const float*)d_in[1];
    const float* value       = (const float*)d_in[2];
    const void*  mask        = d_in[3];
    const float* query_mask  = (const float*)d_in[4];
    const float* Wq = (const float*)d_in[5];
    const float* bq = (const float*)d_in[6];
    const float* Wk = (const float*)d_in[7];
    const float* bk = (const float*)d_in[8];
    const float* Wv = (const float*)d_in[9];
    const float* bv = (const float*)d_in[10];
    const float* Wf = (const float*)d_in[11];
    const float* bf = (const float*)d_in[12];

    float* out  = (float*)d_out;
    float* attn = out + (size_t)B * T * F;

    // 0) mask dtype detection (reset flag, scan first 4MB)
    void* code_addr = nullptr;
    cudaGetSymbolAddress(&code_addr, g_mask_code);
    cudaMemsetAsync(code_addr, 0, sizeof(int));
    detect_mask<<<4096, 256>>>((const unsigned int*)mask);

    const long TT = (long)T * T;
    const long TF = (long)T * F;

    // 1) QKV projections (x3 tf32 for fp32-grade accuracy)
    mma_gemm<false, true, 0><<<dim3(F/BN, MROWS/BM, 1), 256>>>(
        query, query, F, F, 0, 0,  Wq, F, 0, 0,  g_q, F, 0, 0,  F, bq, nullptr, 1.f);
    mma_gemm<false, true, 0><<<dim3(F/BN, MROWS/BM, 1), 256>>>(
        key, key, F, F, 0, 0,      Wk, F, 0, 0,  g_k, F, 0, 0,  F, bk, nullptr, 1.f);
    mma_gemm<false, true, 0><<<dim3(F/BN, MROWS/BM, 1), 256>>>(
        value, value, F, F, 0, 0,  Wv, F, 0, 0,  g_v, F, 0, 0,  F, bv, nullptr, 1.f);

    // 2) scores (NT, x3): attn[z] = q_z @ k_z^T / 8
    mma_gemm<true, true, 1><<<dim3(T/BN, T/BM, H*B), 256>>>(
        g_q, g_q, D, F, TF, D,
        g_k, F, TF, D,
        attn, T, TT, 4*TT,
        D, nullptr, nullptr, 0.125f);

    // 3) masked softmax in place
    softmax_mask<<<H*B*T, 256>>>(attn, mask, query_mask);

    // 4) x = attn @ v  (x1 tf32)
    mma_gemm<false, false, 2><<<dim3(1, T/BM, H*B), 256>>>(
        attn, attn, T, T, TT, 4*TT,
        g_v, F, TF, D,
        g_x, F, TF, D,
        T, nullptr, nullptr, 1.f);

    // 5) out = concat(x, query) @ Wf + bf + query  (x1 tf32)
    mma_gemm<false, false, 3><<<dim3(F/BN, MROWS/BM, 1), 256>>>(
        g_x, query, F, F, 0, 0,
        Wf, F, 0, 0,
        out, F, 0, 0,
        2*F, bf, query, 1.f);
}

// round 5
// speedup vs baseline: 12.7565x; 12.7565x over previous
#include <cuda_runtime.h>
#include <cuda_fp16.h>
#include <math.h>
#include <float.h>
#include <stdint.h>

#define B   4
#define T   1024
#define F   1024
#define H   16
#define D   64
#define MROWS (B*T)       // 4096

// ---------------------------------------------------------------------------
// Scratch (allocation-free rule: __device__ globals)
// ---------------------------------------------------------------------------
__device__ __half g_inq_h[(size_t)MROWS*F], g_inq_l[(size_t)MROWS*F];
__device__ __half g_ink_h[(size_t)MROWS*F], g_ink_l[(size_t)MROWS*F];
__device__ __half g_inv_h[(size_t)MROWS*F], g_inv_l[(size_t)MROWS*F];
__device__ __half g_wq_h[(size_t)F*F], g_wq_l[(size_t)F*F];
__device__ __half g_wk_h[(size_t)F*F], g_wk_l[(size_t)F*F];
__device__ __half g_wv_h[(size_t)F*F], g_wv_l[(size_t)F*F];
__device__ __half g_wf_h[(size_t)2*F*F];
__device__ __half g_qh[(size_t)MROWS*F], g_ql[(size_t)MROWS*F];
__device__ __half g_kh[(size_t)MROWS*F], g_kl[(size_t)MROWS*F];
__device__ float  g_v[(size_t)MROWS*F];
__device__ __half g_vt[(size_t)MROWS*F];
__device__ __half g_xh[(size_t)MROWS*F];
__device__ __half g_attn_h[(size_t)H*B*T*T];
__device__ int    g_mask_code;

// ---------------------------------------------------------------------------
// PTX helpers (legacy pipe only: ldmatrix / mma.sync / cp.async)
// ---------------------------------------------------------------------------
__device__ __forceinline__ uint32_t smem_to_u32(const void* p) {
    uint32_t a;
    asm("{ .reg .u64 tmp; cvta.to.shared.u64 tmp, %1; cvt.u32.u64 %0, tmp; }"
        : "=r"(a) : "l"(p));
    return a;
}
#define SWZ(x) ((x) ^ (((x) >> 3) & 0x70))

#define LDSM_X4(r0,r1,r2,r3,addr) \
    asm volatile("ldmatrix.sync.aligned.m8n8.x4.shared.b16 {%0,%1,%2,%3},[%4];" \
        : "=r"(r0),"=r"(r1),"=r"(r2),"=r"(r3) : "r"(addr))

#define MMA16(d, a, b) \
    asm volatile("mma.sync.aligned.m16n8k16.row.col.f32.f16.f16.f32 " \
        "{%0,%1,%2,%3},{%4,%5,%6,%7},{%8,%9},{%0,%1,%2,%3};" \
        : "+f"((d)[0]),"+f"((d)[1]),"+f"((d)[2]),"+f"((d)[3]) \
        : "r"((a)[0]),"r"((a)[1]),"r"((a)[2]),"r"((a)[3]),"r"((b)[0]),"r"((b)[1]))

#define CP_COMMIT() asm volatile("cp.async.commit_group;" ::: "memory")

// Stage loader: R rows x 64 halves (128B) with SW128 swizzle, 256 threads
template<int R>
__device__ __forceinline__ void ldstage(uint32_t sbase, const __half* __restrict__ g,
                                        int ldg, int t)
{
    #pragma unroll
    for (int i = 0; i < R/32; i++) {
        int c = i * 256 + t;
        int row = c >> 3, ch = c & 7;
        uint32_t off = (uint32_t)(row * 128 + ch * 16);
        uint32_t ad  = sbase + SWZ(off);
        const void* gp = g + (size_t)row * ldg + ch * 8;
        asm volatile("cp.async.cg.shared.global [%0], [%1], 16;" :: "r"(ad), "l"(gp));
    }
}

// ---------------------------------------------------------------------------
// fp16 multistage GEMM: C[m,n] = sum_k A[m,k] * Bt[n,k]  (B given K-major rows)
//   X3: A,B have hi+lo fp16 planes -> 3 mma per product (hh, h*lo, lo*h)
//   A concat: A0 for k<Asplit, A1 after. Per-z: ptr += (z&3)*sL + (z>>2)*sH.
//   EPI: 0 = +bias, write fp16 hi+lo planes (Ch,Cl)
//        1 = +bias, write f32 (Cf)
//        2 = *alpha, write f32
//        3 = write fp16 hi plane (Ch)
//        4 = +bias +resid, write f32
//   Block 128 x BN, 256 threads (8 warps), BK=64, S stages of cp.async.
// ---------------------------------------------------------------------------
template<int BM, int BN, int NT, int S, bool X3, int EPI>
__global__ void __launch_bounds__(256, 1) hgemm(
    const __half* A0h, const __half* A0l,
    const __half* A1h, const __half* A1l, int Asplit, int lda, long saL, long saH,
    const __half* Bh, const __half* Bl, int ldb, long sbL, long sbH,
    float* Cf, __half* Ch, __half* Cl, int ldc, long scL, long scH,
    int K, const float* __restrict__ bias, const float* __restrict__ resid,
    float alpha)
{
    constexpr int WN = BN / 32, WM = 8 / WN, WTM = BM / WM, MI = WTM / 16, NI = 4;
    constexpr int APL = BM * 128 * (X3 ? 2 : 1);
    constexpr int BPL = BN * 128 * (X3 ? 2 : 1);
    constexpr int STG = APL + BPL;

    extern __shared__ __align__(1024) char smem[];
    const uint32_t su = smem_to_u32(smem);

    const int z = blockIdx.z;
    const long za = (long)(z & 3) * saL + (long)(z >> 2) * saH;
    A0h += za;  if (X3) A0l += za;
    const __half* A1hb = A1h ? A1h + za : nullptr;
    const __half* A1lb = (X3 && A1l) ? A1l + za : nullptr;
    const long zb = (long)(z & 3) * sbL + (long)(z >> 2) * sbH;
    Bh += zb;  if (X3) Bl += zb;
    const long zc = (long)(z & 3) * scL + (long)(z >> 2) * scH;
    if (Cf) Cf += zc;  if (Ch) Ch += zc;  if (Cl) Cl += zc;

    const int t = threadIdx.x;
    const int warp = t >> 5, lane = t & 31;
    const int wm = warp % WM, wn = warp / WM;
    const int tile_m = blockIdx.y * BM;

    const int arow = lane & 15,                 akb = (lane >> 4) * 16;
    const int brow = (lane & 7) + ((lane >> 4) << 3), bkb = ((lane >> 3) & 1) * 16;

    const int KT = K >> 6;
    const int total = NT * KT;

    float acc[MI][NI][4];

    for (int tau = 0; tau < total + (S - 1); ++tau) {
        if (tau < total) {
            const int nt = tau / KT, ki = tau - nt * KT, kf = ki << 6;
            const int st = tau % S;
            const int ast = (KT > 1) ? st : 0;
            if (KT > 1 || tau == 0) {
                const __half *Ah, *Al = nullptr;
                if (kf < Asplit) { Ah = A0h + kf; if (X3) Al = A0l + kf; }
                else             { Ah = A1hb + (kf - Asplit); if (X3) Al = A1lb + (kf - Asplit); }
                ldstage<BM>(su + ast * STG, Ah + (size_t)tile_m * lda, lda, t);
                if (X3) ldstage<BM>(su + ast * STG + BM * 128,
                                    Al + (size_t)tile_m * lda, lda, t);
            }
            const int n_base = (blockIdx.x * NT + nt) * BN;
            ldstage<BN>(su + st * STG + APL, Bh + (size_t)n_base * ldb + kf, ldb, t);
            if (X3) ldstage<BN>(su + st * STG + APL + BN * 128,
                                Bl + (size_t)n_base * ldb + kf, ldb, t);
        }
        CP_COMMIT();
        if (tau >= S - 1) {
            asm volatile("cp.async.wait_group %0;" :: "n"(S - 1) : "memory");
            __syncthreads();
            const int tc  = tau - (S - 1);
            const int ntc = tc / KT, kic = tc - ntc * KT;
            const int stc = tc % S, astc = (KT > 1) ? stc : 0;
            if (kic == 0) {
                #pragma unroll
                for (int mi = 0; mi < MI; mi++)
                    #pragma unroll
                    for (int ni = 0; ni < NI; ni++)
                        #pragma unroll
                        for (int q = 0; q < 4; q++) acc[mi][ni][q] = 0.f;
            }
            const uint32_t sA = su + astc * STG;
            const uint32_t sB = su + stc * STG + APL;
            #pragma unroll
            for (int ks = 0; ks < 4; ks++) {
                const int kb2 = ks * 32;
                uint32_t ah[MI][4];
                #pragma unroll
                for (int mi = 0; mi < MI; mi++) {
                    int m0 = wm * WTM + mi * 16;
                    uint32_t off = (uint32_t)((m0 + arow) * 128 + kb2 + akb);
                    LDSM_X4(ah[mi][0], ah[mi][1], ah[mi][2], ah[mi][3], sA + SWZ(off));
                }
                uint32_t bhf[NI][2];
                #pragma unroll
                for (int p = 0; p < 2; p++) {
                    int n0 = wn * 32 + p * 16;
                    uint32_t off = (uint32_t)((n0 + brow) * 128 + kb2 + bkb);
                    uint32_t r0, r1, r2, r3;
                    LDSM_X4(r0, r1, r2, r3, sB + SWZ(off));
                    bhf[2*p][0] = r0; bhf[2*p][1] = r1;
                    bhf[2*p+1][0] = r2; bhf[2*p+1][1] = r3;
                }
                if (X3) {
                    uint32_t al[MI][4], blf[NI][2];
                    #pragma unroll
                    for (int mi = 0; mi < MI; mi++) {
                        int m0 = wm * WTM + mi * 16;
                        uint32_t off = (uint32_t)((m0 + arow) * 128 + kb2 + akb);
                        LDSM_X4(al[mi][0], al[mi][1], al[mi][2], al[mi][3],
                                sA + BM * 128 + SWZ(off));
                    }
                    #pragma unroll
                    for (int p = 0; p < 2; p++) {
                        int n0 = wn * 32 + p * 16;
                        uint32_t off = (uint32_t)((n0 + brow) * 128 + kb2 + bkb);
                        uint32_t r0, r1, r2, r3;
                        LDSM_X4(r0, r1, r2, r3, sB + BN * 128 + SWZ(off));
                        blf[2*p][0] = r0; blf[2*p][1] = r1;
                        blf[2*p+1][0] = r2; blf[2*p+1][1] = r3;
                    }
                    #pragma unroll
                    for (int mi = 0; mi < MI; mi++)
                        #pragma unroll
                        for (int ni = 0; ni < NI; ni++) {
                            MMA16(acc[mi][ni], al[mi], bhf[ni]);
                            MMA16(acc[mi][ni], ah[mi], blf[ni]);
                        }
                }
                #pragma unroll
                for (int mi = 0; mi < MI; mi++)
                    #pragma unroll
                    for (int ni = 0; ni < NI; ni++)
                        MMA16(acc[mi][ni], ah[mi], bhf[ni]);
            }
            if (kic == KT - 1) {
                const int nb = (blockIdx.x * NT + ntc) * BN;
                #pragma unroll
                for (int mi = 0; mi < MI; mi++) {
                    #pragma unroll
                    for (int ni = 0; ni < NI; ni++) {
                        const int col = nb + wn * 32 + ni * 8 + (lane & 3) * 2;
                        #pragma unroll
                        for (int hh = 0; hh < 2; hh++) {
                            const int r = tile_m + wm * WTM + mi * 16 + (lane >> 2) + hh * 8;
                            float v0 = acc[mi][ni][hh * 2 + 0];
                            float v1 = acc[mi][ni][hh * 2 + 1];
                            if (EPI == 0 || EPI == 1 || EPI == 4) {
                                v0 += bias[col]; v1 += bias[col + 1];
                            }
                            if (EPI == 2) { v0 *= alpha; v1 *= alpha; }
                            if (EPI == 4) {
                                v0 += resid[(size_t)r * ldc + col];
                                v1 += resid[(size_t)r * ldc + col + 1];
                            }
                            if (EPI == 0) {
                                __half h0 = __float2half_rn(v0);
                                __half h1 = __float2half_rn(v1);
                                __half2 hp; hp.x = h0; hp.y = h1;
                                *(__half2*)(Ch + (size_t)r * ldc + col) = hp;
                                __half2 lp;
                                lp.x = __float2half_rn(v0 - __half2float(h0));
                                lp.y = __float2half_rn(v1 - __half2float(h1));
                                *(__half2*)(Cl + (size_t)r * ldc + col) = lp;
                            } else if (EPI == 3) {
                                __half2 hp = __floats2half2_rn(v0, v1);
                                *(__half2*)(Ch + (size_t)r * ldc + col) = hp;
                            } else {
                                *(float2*)(Cf + (size_t)r * ldc + col) = make_float2(v0, v1);
                            }
                        }
                    }
                }
            }
            __syncthreads();
        }
    }
}

// ---------------------------------------------------------------------------
// Elementwise split: f32 -> fp16 hi + lo planes (same layout)
// ---------------------------------------------------------------------------
__global__ void fsplit(const float* __restrict__ in,
                       __half* __restrict__ oh, __half* __restrict__ ol)
{
    size_t i = ((size_t)blockIdx.x * 256 + threadIdx.x) * 4;
    float4 v = *(const float4*)(in + i);
    __half h0 = __float2half_rn(v.x), h1 = __float2half_rn(v.y);
    __half h2 = __float2half_rn(v.z), h3 = __float2half_rn(v.w);
    __half2 ph0; ph0.x = h0; ph0.y = h1;
    __half2 ph1; ph1.x = h2; ph1.y = h3;
    ((__half2*)(oh + i))[0] = ph0;
    ((__half2*)(oh + i))[1] = ph1;
    __half2 pl0 = __floats2half2_rn(v.x - __half2float(h0), v.y - __half2float(h1));
    __half2 pl1 = __floats2half2_rn(v.z - __half2float(h2), v.w - __half2float(h3));
    ((__half2*)(ol + i))[0] = pl0;
    ((__half2*)(ol + i))[1] = pl1;
}

// ---------------------------------------------------------------------------
// Transpose + split to fp16 (lo optional): in f32 [z][R][C] -> out [z][C][R]
// ---------------------------------------------------------------------------
__global__ void __launch_bounds__(256) tsplit_h(const float* __restrict__ in,
    __half* __restrict__ oh, __half* __restrict__ ol, int R, int C)
{
    __shared__ float tile[32][33];
    const size_t zo = (size_t)blockIdx.z * R * C;
    in += zo; oh += zo; if (ol) ol += zo;
    const int tx = threadIdx.x & 31, ty = threadIdx.x >> 5;
    const int r0 = blockIdx.y * 32, c0 = blockIdx.x * 32;
    #pragma unroll
    for (int i = 0; i < 4; i++)
        tile[ty + i*8][tx] = in[(size_t)(r0 + ty + i*8) * C + c0 + tx];
    __syncthreads();
    #pragma unroll
    for (int i = 0; i < 4; i++) {
        int c = c0 + ty + i*8;
        int r = r0 + tx;
        float v = tile[tx][ty + i*8];
        __half h = __float2half_rn(v);
        oh[(size_t)c * R + r] = h;
        if (ol) ol[(size_t)c * R + r] = __float2half_rn(v - __half2float(h));
    }
}

// ---------------------------------------------------------------------------
// Mask dtype detection (bool masks may arrive as u8 / i32 / f32)
// ---------------------------------------------------------------------------
__global__ void detect_mask(const unsigned int* __restrict__ m)
{
    unsigned int w = m[blockIdx.x * blockDim.x + threadIdx.x];
    int f = 0;
    if (w == 0x3F800000u)      f = 2;
    else if (w > 1u)           f = 1;
    if (f) atomicOr(&g_mask_code, f);
}

// ---------------------------------------------------------------------------
// Masked softmax (in place on attn) + mask-zeroing + query_mask scale.
// Also emits fp16 copy of attn for the AV GEMM.
// ---------------------------------------------------------------------------
__device__ __forceinline__ float warpMax(float v) {
    #pragma unroll
    for (int o = 16; o; o >>= 1) v = fmaxf(v, __shfl_xor_sync(0xffffffffu, v, o));
    return v;
}
__device__ __forceinline__ float warpSum(float v) {
    #pragma unroll
    for (int o = 16; o; o >>= 1) v += __shfl_xor_sync(0xffffffffu, v, o);
    return v;
}

__global__ void softmax_mask(float* __restrict__ attn,
                             __half* __restrict__ attn_h,
                             const void* __restrict__ mask,
                             const float* __restrict__ query_mask)
{
    const int r  = blockIdx.x;
    const int z  = r >> 10;
    const int bb = z & 3;
    const int i  = r & 1023;
    const size_t base = (size_t)r * T;
    const int t = threadIdx.x;

    float4 s = ((const float4*)(attn + base))[t];

    int m0, m1, m2, m3;
    const int code = g_mask_code;
    if (code & 2) {
        float4 mf = ((const float4*)((const float*)mask + base))[t];
        m0 = (mf.x != 0.f); m1 = (mf.y != 0.f); m2 = (mf.z != 0.f); m3 = (mf.w != 0.f);
    } else if (code & 1) {
        uchar4 mc = ((const uchar4*)((const unsigned char*)mask + base))[t];
        m0 = mc.x; m1 = mc.y; m2 = mc.z; m3 = mc.w;
    } else {
        int4 mi = ((const int4*)((const int*)mask + base))[t];
        m0 = mi.x; m1 = mi.y; m2 = mi.z; m3 = mi.w;
    }

    float v0 = m0 ? -FLT_MAX : s.x;
    float v1 = m1 ? -FLT_MAX : s.y;
    float v2 = m2 ? -FLT_MAX : s.z;
    float v3 = m3 ? -FLT_MAX : s.w;
    float lm = fmaxf(fmaxf(v0, v1), fmaxf(v2, v3));

    __shared__ float red[8];
    float wm = warpMax(lm);
    if ((t & 31) == 0) red[t >> 5] = wm;
    __syncthreads();
    float bmax = red[0];
    #pragma unroll
    for (int w = 1; w < 8; w++) bmax = fmaxf(bmax, red[w]);
    __syncthreads();

    float p0 = m0 ? 0.f : __expf(s.x - bmax);
    float p1 = m1 ? 0.f : __expf(s.y - bmax);
    float p2 = m2 ? 0.f : __expf(s.z - bmax);
    float p3 = m3 ? 0.f : __expf(s.w - bmax);

    float ws = warpSum(p0 + p1 + p2 + p3);
    if ((t & 31) == 0) red[t >> 5] = ws;
    __syncthreads();
    float bsum = 0.f;
    #pragma unroll
    for (int w = 0; w < 8; w++) bsum += red[w];

    float qm  = query_mask[bb * T + i];
    float inv = (bsum > 0.f) ? (qm / bsum) : 0.f;

    float4 o;
    o.x = p0 * inv; o.y = p1 * inv; o.z = p2 * inv; o.w = p3 * inv;
    ((float4*)(attn + base))[t] = o;
    ((__half2*)(attn_h + base))[2*t]   = __floats2half2_rn(o.x, o.y);
    ((__half2*)(attn_h + base))[2*t+1] = __floats2half2_rn(o.z, o.w);
}

// ---------------------------------------------------------------------------
extern "C" void kernel_launch(void* const* d_in, const int* in_sizes, int n_in,
                              void* d_out, int out_size)
{
    const float* query       = (const float*)d_in[0];
    const float* key         = (const float*)d_in[1];
    const float* value       = (const float*)d_in[2];
    const void*  mask        = d_in[3];
    const float* query_mask  = (const float*)d_in[4];
    const float* Wq = (const float*)d_in[5];
    const float* bq = (const float*)d_in[6];
    const float* Wk = (const float*)d_in[7];
    const float* bk = (const float*)d_in[8];
    const float* Wv = (const float*)d_in[9];
    const float* bv = (const float*)d_in[10];
    const float* Wf = (const float*)d_in[11];
    const float* bf = (const float*)d_in[12];

    float* out  = (float*)d_out;
    float* attn = out + (size_t)B * T * F;

    // device symbol addresses
    void* p;
    __half *inqh,*inql,*inkh,*inkl,*invh,*invl;
    __half *wqh,*wql,*wkh,*wkl,*wvh,*wvl,*wfh;
    __half *qh,*ql,*kh,*kl,*vt,*xh,*attnh;
    float *vf;
    cudaGetSymbolAddress(&p, g_inq_h); inqh=(__half*)p;
    cudaGetSymbolAddress(&p, g_inq_l); inql=(__half*)p;
    cudaGetSymbolAddress(&p, g_ink_h); inkh=(__half*)p;
    cudaGetSymbolAddress(&p, g_ink_l); inkl=(__half*)p;
    cudaGetSymbolAddress(&p, g_inv_h); invh=(__half*)p;
    cudaGetSymbolAddress(&p, g_inv_l); invl=(__half*)p;
    cudaGetSymbolAddress(&p, g_wq_h);  wqh=(__half*)p;
    cudaGetSymbolAddress(&p, g_wq_l);  wql=(__half*)p;
    cudaGetSymbolAddress(&p, g_wk_h);  wkh=(__half*)p;
    cudaGetSymbolAddress(&p, g_wk_l);  wkl=(__half*)p;
    cudaGetSymbolAddress(&p, g_wv_h);  wvh=(__half*)p;
    cudaGetSymbolAddress(&p, g_wv_l);  wvl=(__half*)p;
    cudaGetSymbolAddress(&p, g_wf_h);  wfh=(__half*)p;
    cudaGetSymbolAddress(&p, g_qh);    qh=(__half*)p;
    cudaGetSymbolAddress(&p, g_ql);    ql=(__half*)p;
    cudaGetSymbolAddress(&p, g_kh);    kh=(__half*)p;
    cudaGetSymbolAddress(&p, g_kl);    kl=(__half*)p;
    cudaGetSymbolAddress(&p, g_v);     vf=(float*)p;
    cudaGetSymbolAddress(&p, g_vt);    vt=(__half*)p;
    cudaGetSymbolAddress(&p, g_xh);    xh=(__half*)p;
    cudaGetSymbolAddress(&p, g_attn_h);attnh=(__half*)p;

    // dynamic smem opt-in
    constexpr int SM_X3_128 = 2 * (128*256 + 128*256);   // 131072
    constexpr int SM_X1_64  = 3 * (128*128 +  64*128);   //  73728
    constexpr int SM_X1_128 = 3 * (128*128 + 128*128);   //  98304
    cudaFuncSetAttribute((const void*)hgemm<128,128,1,2,true ,0>,
        cudaFuncAttributeMaxDynamicSharedMemorySize, SM_X3_128);
    cudaFuncSetAttribute((const void*)hgemm<128,128,1,2,true ,1>,
        cudaFuncAttributeMaxDynamicSharedMemorySize, SM_X3_128);
    cudaFuncSetAttribute((const void*)hgemm<128,128,4,2,true ,2>,
        cudaFuncAttributeMaxDynamicSharedMemorySize, SM_X3_128);
    cudaFuncSetAttribute((const void*)hgemm<128,64 ,1,3,false,3>,
        cudaFuncAttributeMaxDynamicSharedMemorySize, SM_X1_64);
    cudaFuncSetAttribute((const void*)hgemm<128,128,1,3,false,4>,
        cudaFuncAttributeMaxDynamicSharedMemorySize, SM_X1_128);

    const long TT = (long)T * T;
    const long TF = (long)T * F;

    // 0) mask dtype detection
    void* code_addr = nullptr;
    cudaGetSymbolAddress(&code_addr, g_mask_code);
    cudaMemsetAsync(code_addr, 0, sizeof(int));
    detect_mask<<<4096, 256>>>((const unsigned int*)mask);

    // 1) input splits (f32 -> fp16 hi/lo)
    fsplit<<<4096, 256>>>(query, inqh, inql);
    fsplit<<<4096, 256>>>(key,   inkh, inkl);
    fsplit<<<4096, 256>>>(value, invh, invl);

    // 2) weight transpose + split
    tsplit_h<<<dim3(32, 32, 1), 256>>>(Wq, wqh, wql, F, F);
    tsplit_h<<<dim3(32, 32, 1), 256>>>(Wk, wkh, wkl, F, F);
    tsplit_h<<<dim3(32, 32, 1), 256>>>(Wv, wvh, wvl, F, F);
    tsplit_h<<<dim3(32, 64, 1), 256>>>(Wf, wfh, nullptr, 2*F, F);

    // 3) QKV projections (x3). q,k -> fp16 hi/lo planes; v -> f32.
    hgemm<128,128,1,2,true,0><<<dim3(8, 32, 1), 256, SM_X3_128>>>(
        inqh, inql, inqh, inql, F, F, 0, 0,
        wqh, wql, F, 0, 0,
        nullptr, qh, ql, F, 0, 0, F, bq, nullptr, 1.f);
    hgemm<128,128,1,2,true,0><<<dim3(8, 32, 1), 256, SM_X3_128>>>(
        inkh, inkl, inkh, inkl, F, F, 0, 0,
        wkh, wkl, F, 0, 0,
        nullptr, kh, kl, F, 0, 0, F, bk, nullptr, 1.f);
    hgemm<128,128,1,2,true,1><<<dim3(8, 32, 1), 256, SM_X3_128>>>(
        invh, invl, invh, invl, F, F, 0, 0,
        wvh, wvl, F, 0, 0,
        vf, nullptr, nullptr, F, 0, 0, F, bv, nullptr, 1.f);

    // 4) scores (x3): attn[h*4+b] = q @ k^T / 8
    hgemm<128,128,4,2,true,2><<<dim3(2, 8, 64), 256, SM_X3_128>>>(
        qh, ql, qh, ql, 64, F, TF, D,
        kh, kl, F, TF, D,
        attn, nullptr, nullptr, T, TT, 4*TT, 64, nullptr, nullptr, 0.125f);

    // 5) masked softmax in place (+ fp16 copy)
    softmax_mask<<<H*B*T, 256>>>(attn, attnh, mask, query_mask);

    // 6) v transpose per batch: vt[b][hd][j] = v[b][j][hd] (fp16 hi only)
    tsplit_h<<<dim3(32, 32, 4), 256>>>(vf, vt, nullptr, T, F);

    // 7) x = attn @ v (x1, fp16) -> x hi plane
    hgemm<128,64,1,3,false,3><<<dim3(1, 8, 64), 256, SM_X1_64>>>(
        attnh, nullptr, attnh, nullptr, T, T, TT, 4*TT,
        vt, nullptr, T, (long)F*T, (long)64*T,
        nullptr, xh, nullptr, F, TF, D, T, nullptr, nullptr, 1.f);

    // 8) out = concat(x, query) @ Wf + bf + query (x1, fp16)
    hgemm<128,128,1,3,false,4><<<dim3(8, 32, 1), 256, SM_X1_128>>>(
        xh, nullptr, inqh, nullptr, F, F, 0, 0,
        wfh, nullptr, 2*F, 0, 0,
        out, nullptr, nullptr, F, 0, 0, 2*F, bf, query, 1.f);
}